// round 10
// baseline (speedup 1.0000x reference)
#include <cuda_runtime.h>
#include <cuda_bf16.h>

// kspaceMap: out (32,129,128,128) f32.
//   ch 0..127: sep[b,w,h,w'] = (Re(t)cos(2pi w w'/128) - Im(t)sin(..))/128,
//              t = row DFT_128 of input[:,0].
//   ch 128:    copy of input[b,1,:,:].  mask unused.
// Symmetries: sep[128-w]==sep[w]; value(w,w'+64) = (-1)^w value(w,w').
//
// R10 = R9 + TWO rows (h, h+1) per CTA: all twiddles are h-invariant, so the
// whole prologue + rotation machinery is amortized over 2x the output bytes.
// Store iter: 2 LDS + ~14 ops + 8 STG.128 = 256B. Grid 2048.

#define IM  128
#define BZ  32
#define CH_OUT 129

typedef unsigned long long u64;
#define SGNMASK 0x8000000080000000ull

static __device__ __forceinline__ u64 f2x(float a, float b) {
    u64 r; asm("mov.b64 %0, {%1, %2};" : "=l"(r) : "f"(a), "f"(b)); return r;
}
static __device__ __forceinline__ u64 mul2(u64 a, u64 b) {
    u64 d; asm("mul.rn.f32x2 %0, %1, %2;" : "=l"(d) : "l"(a), "l"(b)); return d;
}
static __device__ __forceinline__ u64 fma2(u64 a, u64 b, u64 c) {
    u64 d; asm("fma.rn.f32x2 %0, %1, %2, %3;" : "=l"(d) : "l"(a), "l"(b), "l"(c)); return d;
}
static __device__ __forceinline__ float2 unpk(u64 v) {
    float2 r; asm("mov.b64 {%0, %1}, %2;" : "=f"(r.x), "=f"(r.y) : "l"(v)); return r;
}

__global__ void __launch_bounds__(256) kspace_kernel(const float* __restrict__ in,
                                                     float* __restrict__ out)
{
    const int blk  = blockIdx.x;          // 0..2047
    const int b    = blk >> 6;
    const int h0   = (blk & 63) * 2;      // rows h0, h0+1
    const int tid  = threadIdx.x;
    const int wj   = tid >> 5;
    const int lane = tid & 31;

    __shared__ float xs[2 * 132];         // 2 rows, pad 132
    __shared__ float yy[2 * 130];         // per row: y+ [0..63], y- [65..128]
    __shared__ float pre[260], pim[260];  // item i = 2*(w + 65*hf) + r
    __shared__ float2 tws2[2 * 65];       // [r][w]

    // ---- ch128 passthrough for both rows (issued first; hides under DFT) ----
    if (tid < 64) {
        const int r = tid >> 5, q = tid & 31;
        const unsigned src = (((unsigned)b * 2 + 1) << 14) + ((unsigned)(h0 + r) << 7) + 4u * q;
        const unsigned dst = (((unsigned)(b * CH_OUT + IM)) << 14) + ((unsigned)(h0 + r) << 7) + 4u * q;
        const float4 cp = __ldcs((const float4*)(in + src));
        __stcs((float4*)(out + dst), cp);
    }

    // ---- stage 2 rows of ch0 (coalesced, 1 float/thread) ----
    {
        const int r = tid >> 7, col = tid & 127;
        xs[r * 132 + col] = in[(((unsigned)b * 2) << 14) + ((unsigned)(h0 + r) << 7) + col];
    }
    __syncthreads();

    // ---- u-fold per row ----
    if (tid < 128) {
        const int r = tid >> 6, u = tid & 63;
        const float a = xs[r * 132 + u], d = xs[r * 132 + u + 64];
        yy[r * 130 + u]      = a + d;
        yy[r * 130 + 65 + u] = a - d;
    }
    __syncthreads();

    // ---- DFT: 260 items x 32 folded MACs. item i: r=i&1, j=i>>1, w=j<65?j:j-65, hf=j>=65 ----
    for (int i = tid; i < 260; i += 256) {
        const int r  = i & 1;
        const int j  = i >> 1;
        const int w  = (j < 65) ? j : j - 65;
        const int hf = (j < 65) ? 0 : 1;
        float SS, SC;  sincospif((float)w * (1.0f / 64.0f), &SS, &SC);
        float s, c;    sincospif((float)(hf * w) * 0.5f, &s, &c);       // u0 = 32*hf (exact)
        const float* yp = yy + r * 130 + (w & 1) * 65 + hf * 32;
        float re = 0.0f, im = 0.0f;
        #pragma unroll 8
        for (int q = 0; q < 32; ++q) {
            const float yv = yp[q];
            re = fmaf(yv,  c, re);
            im = fmaf(yv, -s, im);
            const float cn = fmaf(c, SC, -(s * SS));
            s = fmaf(s, SC, c * SS);
            c = cn;
        }
        pre[i] = re;  pim[i] = im;
    }
    __syncthreads();
    if (tid < 130) {
        const int w = tid >> 1, r = tid & 1;
        const int i0 = 2 * w + r, i1 = 2 * (w + 65) + r;
        tws2[r * 65 + w] = make_float2((pre[i0] + pre[i1]) * (1.0f / IM),
                                       (pim[i0] + pim[i1]) * (1.0f / IM));
    }
    __syncthreads();

    // ---- Store stage: half-warp chain wstart = wj + 8*half, step 16;
    //      lane slot l16 owns w' = 4*l16.. (lo) and +64 (hi = (-1)^w lo); 2 rows. ----
    {
        const int half = lane >> 4;
        const int l16  = lane & 15;
        const int wstart = wj + 8 * half;       // 0..15

        float c0[4], s0[4], sc[4], ss[4];
        #pragma unroll
        for (int k = 0; k < 4; ++k) {
            const int wp = 4 * l16 + k;
            sincospif((float)((wstart * wp) & 127) * (1.0f / 64.0f), &s0[k], &c0[k]);
            sincospif((float)((16 * wp) & 127) * (1.0f / 64.0f), &ss[k], &sc[k]);
        }
        u64 C01 = f2x(c0[0], c0[1]), S01 = f2x(s0[0], s0[1]);
        u64 C23 = f2x(c0[2], c0[3]), S23 = f2x(s0[2], s0[3]);
        const u64 SC01 = f2x(sc[0], sc[1]), SS01 = f2x(ss[0], ss[1]);
        const u64 SC23 = f2x(sc[2], sc[3]), SS23 = f2x(ss[2], ss[3]);
        const u64 sgn  = (wstart & 1) ? SGNMASK : 0ull;
        const bool m0skip = (wstart == 0);

        float* pA = out + (((unsigned)(b * CH_OUT + wstart))        << 14)
                        + ((unsigned)h0 << 7) + 4u * l16;
        float* pM = out + (((unsigned)(b * CH_OUT + (IM - wstart))) << 14)
                        + ((unsigned)h0 << 7) + 4u * l16;

        #pragma unroll
        for (int s = 0; s < 4; ++s) {
            const int w = wstart + 16 * s;                 // <= 63
            const unsigned co = (unsigned)s * 262144u;     // 16 channels
            #pragma unroll
            for (int r = 0; r < 2; ++r) {
                const float2 tt = tws2[r * 65 + w];        // LDS broadcast
                const u64 trx = f2x(tt.x, tt.x);
                const float nti = -tt.y;
                const u64 ntx = f2x(nti, nti);
                const u64 v01 = fma2(ntx, S01, mul2(trx, C01));
                const u64 v23 = fma2(ntx, S23, mul2(trx, C23));
                const u64 h01 = v01 ^ sgn, h23 = v23 ^ sgn;
                const float2 a = unpk(v01), d = unpk(v23);
                const float2 ah = unpk(h01), dh = unpk(h23);
                const float4 vlo = make_float4(a.x, a.y, d.x, d.y);
                const float4 vhi = make_float4(ah.x, ah.y, dh.x, dh.y);
                const unsigned ro = (unsigned)r * 128u;    // row offset (h0 vs h0+1)
                __stcs((float4*)(pA + co + ro), vlo);
                __stcs((float4*)(pA + co + ro + 64u), vhi);
                if (s || !m0skip) {
                    __stcs((float4*)(pM - co + ro), vlo);
                    __stcs((float4*)(pM - co + ro + 64u), vhi);
                }
            }
            // rotate by 16 channels (NS derived by XOR; saves 2 u64 constants)
            const u64 nC01 = fma2(S01, SS01 ^ SGNMASK, mul2(C01, SC01));
            S01 = fma2(C01, SS01, mul2(S01, SC01));
            C01 = nC01;
            const u64 nC23 = fma2(S23, SS23 ^ SGNMASK, mul2(C23, SC23));
            S23 = fma2(C23, SS23, mul2(S23, SC23));
            C23 = nC23;
        }

        // w = 64 tail (warp 0, half 0): mirror(64)==64, store once per row.
        if (wj == 0 && half == 0) {
            #pragma unroll
            for (int r = 0; r < 2; ++r) {
                const float2 tt = tws2[r * 65 + 64];
                const u64 trx = f2x(tt.x, tt.x);
                const float nti = -tt.y;
                const u64 ntx = f2x(nti, nti);
                const u64 v01 = fma2(ntx, S01, mul2(trx, C01));
                const u64 v23 = fma2(ntx, S23, mul2(trx, C23));
                const u64 h01 = v01 ^ sgn, h23 = v23 ^ sgn;
                const float2 a = unpk(v01), d = unpk(v23);
                const float2 ah = unpk(h01), dh = unpk(h23);
                const unsigned ro = (unsigned)r * 128u;
                __stcs((float4*)(pA + 4u * 262144u + ro),       make_float4(a.x, a.y, d.x, d.y));
                __stcs((float4*)(pA + 4u * 262144u + ro + 64u), make_float4(ah.x, ah.y, dh.x, dh.y));
            }
        }
    }
}

extern "C" void kernel_launch(void* const* d_in, const int* in_sizes, int n_in,
                              void* d_out, int out_size)
{
    const float* in  = (const float*)d_in[0];   // (32,2,128,128) f32
    float*       out = (float*)d_out;           // (32,129,128,128) f32
    (void)in_sizes; (void)n_in; (void)out_size;

    kspace_kernel<<<BZ * 64, 256>>>(in, out);
}

// round 11
// speedup vs baseline: 1.0280x; 1.0280x over previous
#include <cuda_runtime.h>
#include <cuda_bf16.h>

// kspaceMap: out (32,129,128,128) f32.
//   ch 0..127: sep[b,w,h,w'] = (Re(t)cos(2pi w w'/128) - Im(t)sin(..))/128,
//              t = row DFT_128 of input[:,0].
//   ch 128:    copy of input[b,1,:,:].  mask unused.
// Symmetries: sep[128-w]==sep[w]; value(w,w'+64) = (-1)^w value(w,w').
//
// R11 = R9 with ALL twiddles sourced from a per-CTA smem table TW[128]
// (one sincospif per thread), and load+fold merged (no xs staging array).
// Store stage identical to R9 (best measured).

#define IM  128
#define BZ  32
#define CH_OUT 129

typedef unsigned long long u64;
#define SGNMASK 0x8000000080000000ull

static __device__ __forceinline__ u64 f2x(float a, float b) {
    u64 r; asm("mov.b64 %0, {%1, %2};" : "=l"(r) : "f"(a), "f"(b)); return r;
}
static __device__ __forceinline__ u64 mul2(u64 a, u64 b) {
    u64 d; asm("mul.rn.f32x2 %0, %1, %2;" : "=l"(d) : "l"(a), "l"(b)); return d;
}
static __device__ __forceinline__ u64 fma2(u64 a, u64 b, u64 c) {
    u64 d; asm("fma.rn.f32x2 %0, %1, %2, %3;" : "=l"(d) : "l"(a), "l"(b), "l"(c)); return d;
}
static __device__ __forceinline__ float2 unpk(u64 v) {
    float2 r; asm("mov.b64 {%0, %1}, %2;" : "=f"(r.x), "=f"(r.y) : "l"(v)); return r;
}

__global__ void __launch_bounds__(256) kspace_kernel(const float* __restrict__ in,
                                                     float* __restrict__ out)
{
    const int bh   = blockIdx.x;
    const int b    = bh >> 7;
    const int h    = bh & (IM - 1);
    const int tid  = threadIdx.x;
    const int wj   = tid >> 5;
    const int lane = tid & 31;

    __shared__ float2 TW[IM];            // (cos,sin)(2*pi*k/128)
    __shared__ float  yy[130];           // y+ [0..63], y- [65..128]
    __shared__ float  pre[130], pim[130];
    __shared__ float2 tws[65];

    // twiddle table: 1 sincospif per thread
    if (tid < IM) {
        float s, c;  sincospif((float)tid * (1.0f / 64.0f), &s, &c);
        TW[tid] = make_float2(c, s);
    }

    // merged load + u-fold (64 threads, 2 LDG each)
    if (tid < 64) {
        const unsigned base = (((unsigned)b * 2) << 14) + ((unsigned)h << 7) + tid;
        const float a = in[base];
        const float d = in[base + 64];
        yy[tid]      = a + d;
        yy[65 + tid] = a - d;
    }
    // concurrent ch128 row copy (warp 5)
    if (wj == 5) {
        const unsigned o = (((unsigned)b * 2 + 1) << 14) + ((unsigned)h << 7) + 4u * lane;
        const float4 cp = __ldcs((const float4*)(in + o));
        __stcs((float4*)(out + ((((unsigned)(b * CH_OUT + IM)) << 14) + ((unsigned)h << 7)) + 4u * lane), cp);
    }
    __syncthreads();

    // ---- DFT (tid<130): item = (bin w, u-half hf), 32 folded MACs ----
    if (tid < 130) {
        const int w  = (tid < 65) ? tid : tid - 65;
        const int hf = (tid < 65) ? 0 : 1;
        const float2 stp = TW[w];                         // step e(2pi w/128)
        const float2 st0 = TW[(32 * hf * w) & (IM - 1)];  // start u0 = 32*hf (exact)
        const float SC = stp.x, SS = stp.y;
        float c = st0.x, s = st0.y;
        const float* yp = yy + (w & 1) * 65 + hf * 32;
        float re = 0.0f, im = 0.0f;
        #pragma unroll 8
        for (int i = 0; i < 32; ++i) {
            const float yv = yp[i];
            re = fmaf(yv,  c, re);
            im = fmaf(yv, -s, im);
            const float cn = fmaf(c, SC, -(s * SS));
            s = fmaf(s, SC, c * SS);
            c = cn;
        }
        pre[tid] = re;  pim[tid] = im;
    }
    __syncthreads();
    if (tid < 65) {
        tws[tid] = make_float2((pre[tid] + pre[tid + 65]) * (1.0f / IM),
                               (pim[tid] + pim[tid + 65]) * (1.0f / IM));
    }
    __syncthreads();

    // ---- Store stage (identical to R9; twiddles from TW) ----
    {
        const int half = lane >> 4;
        const int l16  = lane & 15;
        const int wstart = wj + 8 * half;       // 0..15

        u64 C01, S01, C23, S23, SC01, SS01, SC23, SS23;
        {
            float2 a0 = TW[(wstart * (4 * l16 + 0)) & 127];
            float2 a1 = TW[(wstart * (4 * l16 + 1)) & 127];
            float2 a2 = TW[(wstart * (4 * l16 + 2)) & 127];
            float2 a3 = TW[(wstart * (4 * l16 + 3)) & 127];
            C01 = f2x(a0.x, a1.x);  S01 = f2x(a0.y, a1.y);
            C23 = f2x(a2.x, a3.x);  S23 = f2x(a2.y, a3.y);
            float2 s0 = TW[(16 * (4 * l16 + 0)) & 127];
            float2 s1 = TW[(16 * (4 * l16 + 1)) & 127];
            float2 s2 = TW[(16 * (4 * l16 + 2)) & 127];
            float2 s3 = TW[(16 * (4 * l16 + 3)) & 127];
            SC01 = f2x(s0.x, s1.x);  SS01 = f2x(s0.y, s1.y);
            SC23 = f2x(s2.x, s3.x);  SS23 = f2x(s2.y, s3.y);
        }
        const u64 sgn  = (wstart & 1) ? SGNMASK : 0ull;   // (-1)^w (parity fixed in chain)
        const bool m0skip = (wstart == 0);

        float* pA = out + (((unsigned)(b * CH_OUT + wstart))        << 14)
                        + ((unsigned)h << 7) + 4u * l16;
        float* pM = out + (((unsigned)(b * CH_OUT + (IM - wstart))) << 14)
                        + ((unsigned)h << 7) + 4u * l16;

        #pragma unroll
        for (int s = 0; s < 4; ++s) {
            const int w = wstart + 16 * s;                 // <= 63
            const float2 tt = tws[w];
            const u64 trx = f2x(tt.x, tt.x);
            const float nti = -tt.y;
            const u64 ntx = f2x(nti, nti);
            const u64 v01 = fma2(ntx, S01, mul2(trx, C01));
            const u64 v23 = fma2(ntx, S23, mul2(trx, C23));
            const u64 h01 = v01 ^ sgn, h23 = v23 ^ sgn;
            const float2 a = unpk(v01), d = unpk(v23);
            const float2 ah = unpk(h01), dh = unpk(h23);
            const float4 vlo = make_float4(a.x, a.y, d.x, d.y);
            const float4 vhi = make_float4(ah.x, ah.y, dh.x, dh.y);
            __stcs((float4*)(pA + (unsigned)s * 262144u), vlo);
            __stcs((float4*)(pA + (unsigned)s * 262144u + 64u), vhi);
            if (s || !m0skip) {
                __stcs((float4*)(pM - (unsigned)s * 262144u), vlo);
                __stcs((float4*)(pM - (unsigned)s * 262144u + 64u), vhi);
            }
            const u64 nC01 = fma2(S01, SS01 ^ SGNMASK, mul2(C01, SC01));
            S01 = fma2(C01, SS01, mul2(S01, SC01));
            C01 = nC01;
            const u64 nC23 = fma2(S23, SS23 ^ SGNMASK, mul2(C23, SC23));
            S23 = fma2(C23, SS23, mul2(S23, SC23));
            C23 = nC23;
        }

        // w = 64 tail (warp 0, half 0): mirror(64)==64, store once.
        if (wj == 0 && half == 0) {
            const float2 tt = tws[64];
            const u64 trx = f2x(tt.x, tt.x);
            const float nti = -tt.y;
            const u64 ntx = f2x(nti, nti);
            const u64 v01 = fma2(ntx, S01, mul2(trx, C01));
            const u64 v23 = fma2(ntx, S23, mul2(trx, C23));
            const u64 h01 = v01 ^ sgn, h23 = v23 ^ sgn;
            const float2 a = unpk(v01), d = unpk(v23);
            const float2 ah = unpk(h01), dh = unpk(h23);
            __stcs((float4*)(pA + 4u * 262144u),       make_float4(a.x, a.y, d.x, d.y));
            __stcs((float4*)(pA + 4u * 262144u + 64u), make_float4(ah.x, ah.y, dh.x, dh.y));
        }
    }
}

extern "C" void kernel_launch(void* const* d_in, const int* in_sizes, int n_in,
                              void* d_out, int out_size)
{
    const float* in  = (const float*)d_in[0];   // (32,2,128,128) f32
    float*       out = (float*)d_out;           // (32,129,128,128) f32
    (void)in_sizes; (void)n_in; (void)out_size;

    kspace_kernel<<<BZ * IM, 256>>>(in, out);
}

// round 12
// speedup vs baseline: 1.0418x; 1.0135x over previous
#include <cuda_runtime.h>
#include <cuda_bf16.h>

// kspaceMap: out (32,129,128,128) f32.
//   ch 0..127: sep[b,w,h,w'] = (Re(t)cos(2pi w w'/128) - Im(t)sin(..))/128,
//              t = row DFT_128 of input[:,0].
//   ch 128:    copy of input[b,1,:,:].  mask unused.
// Symmetries: sep[128-w]==sep[w]; value(w,w'+64) = (-1)^w value(w,w').
//
// R12 = R11 squeezed to 32 regs for 8 CTAs/SM (store-latency hiding):
//  - launch_bounds(256, 8)
//  - chain-23 rotation derived from chain-01 step constants via quarter-turn
//    identity (cos(t+pi/2), sin(t+pi/2)) = (-sin t, cos t)  -> 4 regs saved
//  - stores addressed as out + unsigned offset (single base pointer)

#define IM  128
#define BZ  32
#define CH_OUT 129

typedef unsigned long long u64;
#define SGNMASK 0x8000000080000000ull

static __device__ __forceinline__ u64 f2x(float a, float b) {
    u64 r; asm("mov.b64 %0, {%1, %2};" : "=l"(r) : "f"(a), "f"(b)); return r;
}
static __device__ __forceinline__ u64 mul2(u64 a, u64 b) {
    u64 d; asm("mul.rn.f32x2 %0, %1, %2;" : "=l"(d) : "l"(a), "l"(b)); return d;
}
static __device__ __forceinline__ u64 fma2(u64 a, u64 b, u64 c) {
    u64 d; asm("fma.rn.f32x2 %0, %1, %2, %3;" : "=l"(d) : "l"(a), "l"(b), "l"(c)); return d;
}
static __device__ __forceinline__ float2 unpk(u64 v) {
    float2 r; asm("mov.b64 {%0, %1}, %2;" : "=f"(r.x), "=f"(r.y) : "l"(v)); return r;
}

__global__ void __launch_bounds__(256, 8) kspace_kernel(const float* __restrict__ in,
                                                        float* __restrict__ out)
{
    const int bh   = blockIdx.x;
    const int b    = bh >> 7;
    const int h    = bh & (IM - 1);
    const int tid  = threadIdx.x;
    const int wj   = tid >> 5;
    const int lane = tid & 31;

    __shared__ float2 TW[IM];            // (cos,sin)(2*pi*k/128)
    __shared__ float  yy[130];           // y+ [0..63], y- [65..128]
    __shared__ float  pre[130], pim[130];
    __shared__ float2 tws[65];

    if (tid < IM) {
        float s, c;  sincospif((float)tid * (1.0f / 64.0f), &s, &c);
        TW[tid] = make_float2(c, s);
    }

    // merged load + u-fold (64 threads, 2 LDG each)
    if (tid < 64) {
        const unsigned base = (((unsigned)b * 2) << 14) + ((unsigned)h << 7) + tid;
        const float a = in[base];
        const float d = in[base + 64];
        yy[tid]      = a + d;
        yy[65 + tid] = a - d;
    }
    // concurrent ch128 row copy (warp 5)
    if (wj == 5) {
        const unsigned o = (((unsigned)b * 2 + 1) << 14) + ((unsigned)h << 7) + 4u * lane;
        const float4 cp = __ldcs((const float4*)(in + o));
        __stcs((float4*)(out + ((((unsigned)(b * CH_OUT + IM)) << 14) + ((unsigned)h << 7)) + 4u * lane), cp);
    }
    __syncthreads();

    // ---- DFT (tid<130): item = (bin w, u-half hf), 32 folded MACs ----
    if (tid < 130) {
        const int w  = (tid < 65) ? tid : tid - 65;
        const int hf = (tid < 65) ? 0 : 1;
        const float2 stp = TW[w];
        const float2 st0 = TW[(32 * hf * w) & (IM - 1)];
        const float SC = stp.x, SS = stp.y;
        float c = st0.x, s = st0.y;
        const float* yp = yy + (w & 1) * 65 + hf * 32;
        float re = 0.0f, im = 0.0f;
        #pragma unroll 8
        for (int i = 0; i < 32; ++i) {
            const float yv = yp[i];
            re = fmaf(yv,  c, re);
            im = fmaf(yv, -s, im);
            const float cn = fmaf(c, SC, -(s * SS));
            s = fmaf(s, SC, c * SS);
            c = cn;
        }
        pre[tid] = re;  pim[tid] = im;
    }
    __syncthreads();
    if (tid < 65) {
        tws[tid] = make_float2((pre[tid] + pre[tid + 65]) * (1.0f / IM),
                               (pim[tid] + pim[tid + 65]) * (1.0f / IM));
    }
    __syncthreads();

    // ---- Store stage ----
    {
        const int half = lane >> 4;
        const int l16  = lane & 15;
        const int wstart = wj + 8 * half;       // 0..15

        u64 C01, S01, C23, S23, SC01, SS01;
        {
            float2 a0 = TW[(wstart * (4 * l16 + 0)) & 127];
            float2 a1 = TW[(wstart * (4 * l16 + 1)) & 127];
            float2 a2 = TW[(wstart * (4 * l16 + 2)) & 127];
            float2 a3 = TW[(wstart * (4 * l16 + 3)) & 127];
            C01 = f2x(a0.x, a1.x);  S01 = f2x(a0.y, a1.y);
            C23 = f2x(a2.x, a3.x);  S23 = f2x(a2.y, a3.y);
            float2 s0 = TW[(16 * (4 * l16 + 0)) & 127];
            float2 s1 = TW[(16 * (4 * l16 + 1)) & 127];
            SC01 = f2x(s0.x, s1.x);  SS01 = f2x(s0.y, s1.y);
            // chain-23 step = chain-01 step rotated by pi/2:
            //   cos23 = -SS01, sin23 = SC01  (derived at use via XOR)
        }
        const u64 sgn  = (wstart & 1) ? SGNMASK : 0ull;
        const bool m0skip = (wstart == 0);

        const unsigned offA = (((unsigned)(b * CH_OUT + wstart))        << 14)
                            + ((unsigned)h << 7) + 4u * l16;
        const unsigned offM = (((unsigned)(b * CH_OUT + (IM - wstart))) << 14)
                            + ((unsigned)h << 7) + 4u * l16;

        #pragma unroll
        for (int s = 0; s < 4; ++s) {
            const int w = wstart + 16 * s;                 // <= 63
            const float2 tt = tws[w];
            const u64 trx = f2x(tt.x, tt.x);
            const float nti = -tt.y;
            const u64 ntx = f2x(nti, nti);
            const u64 v01 = fma2(ntx, S01, mul2(trx, C01));
            const u64 v23 = fma2(ntx, S23, mul2(trx, C23));
            const u64 h01 = v01 ^ sgn, h23 = v23 ^ sgn;
            const float2 a = unpk(v01), d = unpk(v23);
            const float2 ah = unpk(h01), dh = unpk(h23);
            const float4 vlo = make_float4(a.x, a.y, d.x, d.y);
            const float4 vhi = make_float4(ah.x, ah.y, dh.x, dh.y);
            __stcs((float4*)(out + offA + (unsigned)s * 262144u), vlo);
            __stcs((float4*)(out + offA + (unsigned)s * 262144u + 64u), vhi);
            if (s || !m0skip) {
                __stcs((float4*)(out + offM - (unsigned)s * 262144u), vlo);
                __stcs((float4*)(out + offM - (unsigned)s * 262144u + 64u), vhi);
            }
            // rotate chain 01 by step (SC01,SS01)
            const u64 nC01 = fma2(S01, SS01 ^ SGNMASK, mul2(C01, SC01));
            S01 = fma2(C01, SS01, mul2(S01, SC01));
            C01 = nC01;
            // rotate chain 23 by step (-SS01, SC01)  [quarter-turn identity]
            const u64 nC23 = fma2(C23, SS01, mul2(S23, SC01)) ^ SGNMASK;
            S23 = fma2(S23, SS01 ^ SGNMASK, mul2(C23, SC01));
            C23 = nC23;
        }

        // w = 64 tail (warp 0, half 0): mirror(64)==64, store once.
        if (wj == 0 && half == 0) {
            const float2 tt = tws[64];
            const u64 trx = f2x(tt.x, tt.x);
            const float nti = -tt.y;
            const u64 ntx = f2x(nti, nti);
            const u64 v01 = fma2(ntx, S01, mul2(trx, C01));
            const u64 v23 = fma2(ntx, S23, mul2(trx, C23));
            const u64 h01 = v01 ^ sgn, h23 = v23 ^ sgn;
            const float2 a = unpk(v01), d = unpk(v23);
            const float2 ah = unpk(h01), dh = unpk(h23);
            __stcs((float4*)(out + offA + 4u * 262144u),       make_float4(a.x, a.y, d.x, d.y));
            __stcs((float4*)(out + offA + 4u * 262144u + 64u), make_float4(ah.x, ah.y, dh.x, dh.y));
        }
    }
}

extern "C" void kernel_launch(void* const* d_in, const int* in_sizes, int n_in,
                              void* d_out, int out_size)
{
    const float* in  = (const float*)d_in[0];   // (32,2,128,128) f32
    float*       out = (float*)d_out;           // (32,129,128,128) f32
    (void)in_sizes; (void)n_in; (void)out_size;

    kspace_kernel<<<BZ * IM, 256>>>(in, out);
}